// round 15
// baseline (speedup 1.0000x reference)
#include <cuda_runtime.h>
#include <cuda_fp16.h>
#include <cstdint>

#define HW    1560
#define TQ    2
#define QTOT  3120
#define KTOT  12480
#define HEADS 12
#define DH    128
#define DIM   1536

// ---------------- scratch (device globals; no allocation allowed) ----------------
__device__ __half g_q[QTOT * DIM];
__device__ __half g_k[KTOT * DIM];
__device__ __half g_v[KTOT * DIM];
__device__ __half g_attn[QTOT * DIM];
__device__ __half g_hid[QTOT * DIM];
__device__ __half g_his[KTOT * DIM];
__device__ __half g_wq[DIM * DIM];
__device__ __half g_wk[DIM * DIM];
__device__ __half g_wv[DIM * DIM];
__device__ __half g_wo[DIM * DIM];

// ---------------- helpers ----------------
__device__ __forceinline__ void mma_f16(float* d, const unsigned* a, unsigned b0, unsigned b1) {
    asm volatile(
        "mma.sync.aligned.m16n8k16.row.col.f32.f16.f16.f32 "
        "{%0,%1,%2,%3}, {%4,%5,%6,%7}, {%8,%9}, {%0,%1,%2,%3};"
        : "+f"(d[0]), "+f"(d[1]), "+f"(d[2]), "+f"(d[3])
        : "r"(a[0]), "r"(a[1]), "r"(a[2]), "r"(a[3]), "r"(b0), "r"(b1));
}

__device__ __forceinline__ uint32_t smem_u32(const void* p) {
    uint32_t a;
    asm("{ .reg .u64 t; cvta.to.shared.u64 t, %1; cvt.u32.u64 %0, t; }" : "=r"(a) : "l"(p));
    return a;
}

__device__ __forceinline__ void ldsm_x4(unsigned* r, uint32_t addr) {
    asm volatile("ldmatrix.sync.aligned.m8n8.x4.shared.b16 {%0,%1,%2,%3}, [%4];"
                 : "=r"(r[0]), "=r"(r[1]), "=r"(r[2]), "=r"(r[3]) : "r"(addr));
}

__device__ __forceinline__ void ldsm_x4_trans(unsigned* r, uint32_t addr) {
    asm volatile("ldmatrix.sync.aligned.m8n8.x4.trans.shared.b16 {%0,%1,%2,%3}, [%4];"
                 : "=r"(r[0]), "=r"(r[1]), "=r"(r[2]), "=r"(r[3]) : "r"(addr));
}

__device__ __forceinline__ void cp_async16(uint32_t dst, const void* src, bool valid) {
    int sz = valid ? 16 : 0;
    asm volatile("cp.async.cg.shared.global [%0], [%1], 16, %2;"
                 :: "r"(dst), "l"(src), "r"(sz) : "memory");
}
__device__ __forceinline__ void cp_commit() {
    asm volatile("cp.async.commit_group;" ::: "memory");
}
__device__ __forceinline__ void cp_wait1() {
    asm volatile("cp.async.wait_group 1;" ::: "memory");
}
__device__ __forceinline__ void cp_wait0() {
    asm volatile("cp.async.wait_group 0;" ::: "memory");
}

__device__ __forceinline__ uint2 f4_to_h4(float4 v) {
    __half2 h0 = __float22half2_rn(make_float2(v.x, v.y));
    __half2 h1 = __float22half2_rn(make_float2(v.z, v.w));
    uint2 r;
    r.x = *(unsigned*)&h0;
    r.y = *(unsigned*)&h1;
    return r;
}

__device__ __forceinline__ bool block_needed(int b, const int* __restrict__ sel) {
    return (sel[0] == b) | (sel[1] == b) | (sel[2] == b) | (sel[3] == b);
}

// ---------------- fused one-time fp32 -> fp16 conversions (single launch) ----------------
__global__ __launch_bounds__(192) void cvt_all(
    const float* __restrict__ Wq, const float* __restrict__ Wk,
    const float* __restrict__ Wv, const float* __restrict__ Wo,
    const float* __restrict__ hidden, const float* __restrict__ history,
    __half* __restrict__ wq, __half* __restrict__ wk,
    __half* __restrict__ wv, __half* __restrict__ wo,
    __half* __restrict__ hid, __half* __restrict__ his,
    const int* __restrict__ sel)
{
    int b = blockIdx.x;
    const float* src;
    __half* dst;
    long row;
    if (b < 4 * DIM) {
        if (b < DIM)          { src = Wq; dst = wq; row = b; }
        else if (b < 2 * DIM) { src = Wk; dst = wk; row = b - DIM; }
        else if (b < 3 * DIM) { src = Wv; dst = wv; row = b - 2 * DIM; }
        else                  { src = Wo; dst = wo; row = b - 3 * DIM; }
    } else if (b < 4 * DIM + QTOT) {
        src = hidden; dst = hid; row = b - 4 * DIM;
    } else {
        row = b - (4 * DIM + QTOT);
        if (!block_needed((int)(row / HW), sel)) return;
        src = history; dst = his;
    }
    const int c = threadIdx.x * 8;
    const float* s = src + row * DIM + c;
    float4 f0 = *(const float4*)s;
    float4 f1 = *(const float4*)(s + 4);
    uint2 h0 = f4_to_h4(f0), h1 = f4_to_h4(f1);
    *(uint4*)(dst + row * DIM + c) = make_uint4(h0.x, h0.y, h1.x, h1.y);
}

// ---------------- GEMM core (unchanged) ----------------
#define GEMM_STAGE_H (128 * 40)
#define GEMM_SMEM    (2 * 2 * GEMM_STAGE_H * 2)   // 40960 bytes

template <bool OUT_HALF>
__device__ __forceinline__ void gemm_core(
    const __half* __restrict__ A, const __half* __restrict__ W,
    const float* __restrict__ bias, void* __restrict__ Cv,
    int M, int N, int K, const int* __restrict__ sel)
{
    extern __shared__ __half gh[];
    float*  Cf = (float*)Cv;
    __half* Ch = (__half*)Cv;

    const int bm = blockIdx.y * 128, bn = blockIdx.x * 128;

    if (sel) {
        int b0 = bm / HW;
        int b1 = (bm + 127) / HW;
        if (!block_needed(b0, sel) && !block_needed(b1, sel)) return;
    }

    const int tid  = threadIdx.x;
    const int warp = tid >> 5, lane = tid & 31;
    const int g = lane >> 2, t4 = lane & 3;
    const int wm = warp >> 2, wn = warp & 3;

    float acc[4][4][4] = {};

    const int lc2 = (tid & 3) * 8;
    const int lr2 = tid >> 2;

    const int i8 = lane >> 3, r8 = lane & 7;
    const int a_row = (i8 & 1) * 8 + r8;
    const int a_ko  = (i8 >> 1) * 8;
    const uint32_t gh_b = smem_u32(gh);
    uint32_t aoff[4], boff[2];
    #pragma unroll
    for (int mt = 0; mt < 4; mt++)
        aoff[mt] = ((wm * 64 + mt * 16 + a_row) * 40 + a_ko) * 2;
    #pragma unroll
    for (int np = 0; np < 2; np++) {
        int b_row = (i8 >> 1) * 8 + r8;
        int b_ko  = (i8 & 1) * 8;
        boff[np] = ((wn * 32 + np * 16 + b_row) * 40 + b_ko) * 2;
    }

    uint4 aH[2], wH[2];
    const uint4 z4 = make_uint4(0u, 0u, 0u, 0u);

    #pragma unroll
    for (int i = 0; i < 2; i++) {
        int row = lr2 + 64 * i;
        long ar = bm + row;
        aH[i] = (ar < M) ? *(const uint4*)(A + ar * (long)K + lc2) : z4;
        wH[i] = *(const uint4*)(W + (long)(bn + row) * K + lc2);
    }

    {
        __half* As = gh;
        __half* Ws = gh + GEMM_STAGE_H;
        #pragma unroll
        for (int i = 0; i < 2; i++) {
            int row = lr2 + 64 * i;
            *(uint4*)&As[row * 40 + lc2] = aH[i];
            *(uint4*)&Ws[row * 40 + lc2] = wH[i];
        }
    }
    __syncthreads();

    const int KT = K >> 5;
    for (int kt = 0; kt < KT; kt++) {
        const uint32_t As_b = gh_b + (kt & 1) * (4 * GEMM_STAGE_H);
        const uint32_t Ws_b = As_b + 2 * GEMM_STAGE_H;

        if (kt + 1 < KT) {
            int k0 = (kt + 1) << 5;
            #pragma unroll
            for (int i = 0; i < 2; i++) {
                int row = lr2 + 64 * i;
                long ar = bm + row;
                aH[i] = (ar < M) ? *(const uint4*)(A + ar * (long)K + k0 + lc2) : z4;
                wH[i] = *(const uint4*)(W + (long)(bn + row) * K + k0 + lc2);
            }
        }

        #pragma unroll
        for (int kk = 0; kk < 2; kk++) {
            const uint32_t kB = kk * 32;
            unsigned a[4][4], b[2][4];
            #pragma unroll
            for (int mt = 0; mt < 4; mt++) ldsm_x4(a[mt], As_b + aoff[mt] + kB);
            #pragma unroll
            for (int np = 0; np < 2; np++) ldsm_x4(b[np], Ws_b + boff[np] + kB);
            #pragma unroll
            for (int nt = 0; nt < 4; nt++) {
                unsigned b0 = b[nt >> 1][(nt & 1) * 2];
                unsigned b1 = b[nt >> 1][(nt & 1) * 2 + 1];
                #pragma unroll
                for (int mt = 0; mt < 4; mt++)
                    mma_f16(acc[mt][nt], a[mt], b0, b1);
            }
        }

        if (kt + 1 < KT) {
            __half* Asn = gh + ((kt + 1) & 1) * 2 * GEMM_STAGE_H;
            __half* Wsn = Asn + GEMM_STAGE_H;
            #pragma unroll
            for (int i = 0; i < 2; i++) {
                int row = lr2 + 64 * i;
                *(uint4*)&Asn[row * 40 + lc2] = aH[i];
                *(uint4*)&Wsn[row * 40 + lc2] = wH[i];
            }
        }
        __syncthreads();
    }

    #pragma unroll
    for (int mt = 0; mt < 4; mt++) {
        int r = bm + wm * 64 + mt * 16 + g;
        #pragma unroll
        for (int nt = 0; nt < 4; nt++) {
            int c = bn + wn * 32 + nt * 8 + t4 * 2;
            float b0 = bias[c], b1 = bias[c + 1];
            if (OUT_HALF) {
                if (r < M) {
                    __half2 h = __floats2half2_rn(acc[mt][nt][0] + b0, acc[mt][nt][1] + b1);
                    *(unsigned*)(Ch + (long)r * N + c) = *(unsigned*)&h;
                }
                if (r + 8 < M) {
                    __half2 h = __floats2half2_rn(acc[mt][nt][2] + b0, acc[mt][nt][3] + b1);
                    *(unsigned*)(Ch + (long)(r + 8) * N + c) = *(unsigned*)&h;
                }
            } else {
                if (r < M)
                    *(float2*)(Cf + (long)r * N + c) =
                        make_float2(acc[mt][nt][0] + b0, acc[mt][nt][1] + b1);
                if (r + 8 < M)
                    *(float2*)(Cf + (long)(r + 8) * N + c) =
                        make_float2(acc[mt][nt][2] + b0, acc[mt][nt][3] + b1);
            }
        }
    }
}

__global__ __launch_bounds__(256, 2) void gemm_qkv(
    const __half* __restrict__ hid, const __half* __restrict__ his,
    const __half* __restrict__ wq, const __half* __restrict__ wk,
    const __half* __restrict__ wv,
    const float* __restrict__ bq, const float* __restrict__ bk,
    const float* __restrict__ bv,
    __half* __restrict__ q, __half* __restrict__ k, __half* __restrict__ v,
    const int* __restrict__ sel)
{
    const int z = blockIdx.z;
    if (z == 0) {
        if (blockIdx.y >= 25) return;
        gemm_core<true>(hid, wq, bq, q, QTOT, DIM, DIM, nullptr);
    } else if (z == 1) {
        gemm_core<true>(his, wk, bk, k, KTOT, DIM, DIM, sel);
    } else {
        gemm_core<true>(his, wv, bv, v, KTOT, DIM, DIM, sel);
    }
}

__global__ __launch_bounds__(256, 2) void gemm_o(
    const __half* __restrict__ A, const __half* __restrict__ W,
    const float* __restrict__ bias, float* __restrict__ C)
{
    gemm_core<false>(A, W, bias, C, QTOT, DIM, DIM, nullptr);
}

// ---------------- fused RMSNorm + RoPE for q AND k in one launch ----------------
__global__ __launch_bounds__(384) void rmsnorm_all(
    __half* __restrict__ q, __half* __restrict__ k,
    const float* __restrict__ gq, const float* __restrict__ gk,
    const float* __restrict__ fc, const float* __restrict__ fs,
    const float* __restrict__ fch, const float* __restrict__ fsh,
    const int* __restrict__ sel)
{
    __shared__ float red[12];
    __shared__ float rinv_s;
    int row = blockIdx.x;
    const int tid = threadIdx.x;

    __half* x;
    const float *gamma, *fcp, *fsp;
    if (row < QTOT) {
        x = q; gamma = gq; fcp = fc; fsp = fs;
    } else {
        row -= QTOT;
        if (!block_needed(row / HW, sel)) return;
        x = k; gamma = gk; fcp = fch; fsp = fsh;
    }

    uint2 u = *(uint2*)(x + (long)row * DIM + tid * 4);
    __half2 h01 = *(__half2*)&u.x;
    __half2 h23 = *(__half2*)&u.y;
    float2 f01 = __half22float2(h01);
    float2 f23 = __half22float2(h23);

    float ss = f01.x * f01.x + f01.y * f01.y + f23.x * f23.x + f23.y * f23.y;
    #pragma unroll
    for (int s = 16; s > 0; s >>= 1) ss += __shfl_xor_sync(0xffffffffu, ss, s);
    if ((tid & 31) == 0) red[tid >> 5] = ss;
    __syncthreads();
    if (tid < 32) {
        float t = (tid < 12) ? red[tid] : 0.f;
        #pragma unroll
        for (int s = 16; s > 0; s >>= 1) t += __shfl_xor_sync(0xffffffffu, t, s);
        if (tid == 0) rinv_s = rsqrtf(t * (1.0f / DIM) + 1e-5f);
    }
    __syncthreads();
    float r = rinv_s;

    float4 g4 = *(const float4*)(gamma + tid * 4);
    float x0 = f01.x * r * g4.x, x1 = f01.y * r * g4.y;
    float x2 = f23.x * r * g4.z, x3 = f23.y * r * g4.w;

    int hd = (tid * 4) & (DH - 1);
    float4 c4 = *(const float4*)(fcp + (long)row * DH + hd);
    float4 s4 = *(const float4*)(fsp + (long)row * DH + hd);
    float o0 = x0 * c4.x - x1 * s4.y;
    float o1 = x0 * s4.y + x1 * c4.x;
    float o2 = x2 * c4.z - x3 * s4.w;
    float o3 = x2 * s4.w + x3 * c4.z;

    __half2 ho01 = __floats2half2_rn(o0, o1);
    __half2 ho23 = __floats2half2_rn(o2, o3);
    *(uint2*)(x + (long)row * DIM + tid * 4) =
        make_uint2(*(unsigned*)&ho01, *(unsigned*)&ho23);
}

// ---------------- fused block-sparse attention: cp.async 2-stage + softmax/PV interleave ------
#define AQ_OFF   0
#define AK_OFF   34816
#define KV_STAGE 17408
#define AV_OFF   (AK_OFF + 2 * KV_STAGE)
#define ATT_SMEM (AV_OFF + 2 * KV_STAGE)   // 104448

#define N_TILES 25   // ceil(HW/64)

__global__ __launch_bounds__(256, 2) void attention_kernel(
    const __half* __restrict__ q, const __half* __restrict__ k,
    const __half* __restrict__ v, const int* __restrict__ sel,
    __half* __restrict__ out)
{
    extern __shared__ char asm_[];
    __half* Qh = (__half*)(asm_ + AQ_OFF);

    const int qb = blockIdx.x, t = blockIdx.y, h = blockIdx.z;
    const int tid = threadIdx.x, warp = tid >> 5, lane = tid & 31;
    const int g = lane >> 2, t4 = lane & 3;

    const int i8 = lane >> 3, r8 = lane & 7;
    const uint32_t smb = smem_u32(asm_);
    const uint32_t qoff = smb + ((warp * 16 + (i8 & 1) * 8 + r8) * 136 + (i8 >> 1) * 8) * 2;
    uint32_t koff_l[4];
    #pragma unroll
    for (int np = 0; np < 4; np++)
        koff_l[np] = ((np * 16 + (i8 >> 1) * 8 + r8) * 136 + (i8 & 1) * 8) * 2;
    const uint32_t voff_l = (((i8 & 1) * 8 + r8) * 136 + (i8 >> 1) * 8) * 2;

    const uint4 z4 = make_uint4(0u, 0u, 0u, 0u);

    // load Q tile (fp16, zero-fill tail rows)
    const __half* qbase = q + (long)(t * HW) * DIM + (long)h * DH;
    {
        const int c8 = (tid & 15) * 8;
        const int lr0q = tid >> 4;
        #pragma unroll
        for (int i = 0; i < 8; i++) {
            int r = lr0q + i * 16;
            int qr = qb * 128 + r;
            uint4 val = (qr < HW) ? *(const uint4*)(qbase + (long)qr * DIM + c8) : z4;
            *(uint4*)&Qh[r * 136 + c8] = val;
        }
    }

    float oacc[16][4] = {};
    float rp0 = 0.f, rp1 = 0.f;

    int s0 = sel[t * 2 + 0]; if (s0 < 0) s0 = 0;
    int s1 = sel[t * 2 + 1];
    int nb = (s1 >= 0) ? 2 : 1;
    const int ntile = nb * N_TILES;

    const __half* kb0 = k + (long)s0 * HW * DIM + (long)h * DH;
    const __half* vb0 = v + (long)s0 * HW * DIM + (long)h * DH;
    const __half* kb1 = (nb == 2) ? (k + (long)s1 * HW * DIM + (long)h * DH) : kb0;
    const __half* vb1 = (nb == 2) ? (v + (long)s1 * HW * DIM + (long)h * DH) : vb0;

    const int lc8 = (tid & 15) * 8;
    const int lr0 = tid >> 4;

    auto issue_tile = [&](int ti) {
        int bi = ti / N_TILES;
        int n0 = (ti - bi * N_TILES) * 64;
        const __half* kbp = bi ? kb1 : kb0;
        const __half* vbp = bi ? vb1 : vb0;
        uint32_t kdst = smb + AK_OFF + (ti & 1) * KV_STAGE;
        uint32_t vdst = smb + AV_OFF + (ti & 1) * KV_STAGE;
        #pragma unroll
        for (int i = 0; i < 4; i++) {
            int r = lr0 + i * 16;
            int kr = n0 + r;
            bool valid = kr < HW;
            long off = valid ? ((long)kr * DIM + lc8) : 0;
            uint32_t d = (r * 136 + lc8) * 2;
            cp_async16(kdst + d, kbp + off, valid);
            cp_async16(vdst + d, vbp + off, valid);
        }
        cp_commit();
    };

    __syncthreads();
    issue_tile(0);

    const float SC   = 0.08838834764831843f * 1.4426950408889634f;
    const float OFFL = 4.0f * 1.4426950408889634f;

    for (int ti = 0; ti < ntile; ti++) {
        if (ti + 1 < ntile) { issue_tile(ti + 1); cp_wait1(); }
        else                { cp_wait0(); }
        __syncthreads();

        const uint32_t Kb = smb + AK_OFF + (ti & 1) * KV_STAGE;
        const uint32_t Vb = smb + AV_OFF + (ti & 1) * KV_STAGE;
        const int bi = ti / N_TILES;
        const int n0 = (ti - bi * N_TILES) * 64;

        // ---- QK^T via ldmatrix ----
        float sacc[8][4] = {};
        #pragma unroll
        for (int ks = 0; ks < 8; ks++) {
            const uint32_t kB = ks * 32;
            unsigned a[4], b[4][4];
            ldsm_x4(a, qoff + kB);
            #pragma unroll
            for (int np = 0; np < 4; np++) ldsm_x4(b[np], Kb + koff_l[np] + kB);
            #pragma unroll
            for (int nt = 0; nt < 8; nt++) {
                unsigned b0 = b[nt >> 1][(nt & 1) * 2];
                unsigned b1 = b[nt >> 1][(nt & 1) * 2 + 1];
                mma_f16(sacc[nt], a, b0, b1);
            }
        }

        // ---- softmax(kp) interleaved with PV(kp): tensor pipe stays fed ----
        #pragma unroll
        for (int kp = 0; kp < 4; kp++) {
            // softmax for the two nt feeding this kp's A-fragment
            unsigned ap[4];
            #pragma unroll
            for (int j = 0; j < 2; j++) {
                int nt = 2 * kp + j;
                int cn = nt * 8 + 2 * t4;
                bool m0 = (n0 + cn) < HW, m1 = (n0 + cn + 1) < HW;
                float p0 = m0 ? exp2f(fmaf(sacc[nt][0], SC, -OFFL)) : 0.f;
                float p1 = m1 ? exp2f(fmaf(sacc[nt][1], SC, -OFFL)) : 0.f;
                float p2 = m0 ? exp2f(fmaf(sacc[nt][2], SC, -OFFL)) : 0.f;
                float p3 = m1 ? exp2f(fmaf(sacc[nt][3], SC, -OFFL)) : 0.f;
                rp0 += p0 + p1;
                rp1 += p2 + p3;
                __half2 h01 = __floats2half2_rn(p0, p1);
                __half2 h23 = __floats2half2_rn(p2, p3);
                ap[j * 2 + 0] = *(unsigned*)&h01;
                ap[j * 2 + 1] = *(unsigned*)&h23;
            }
            // PV for kp with 1-ahead ldsm prefetch
            const uint32_t kbase = Vb + voff_l + kp * (16 * 136 * 2);
            unsigned bv[2][4];
            ldsm_x4_trans(bv[0], kbase);
            #pragma unroll
            for (int nt16 = 0; nt16 < 8; nt16++) {
                if (nt16 + 1 < 8) ldsm_x4_trans(bv[(nt16 + 1) & 1], kbase + (nt16 + 1) * 32);
                const unsigned* bvc = bv[nt16 & 1];
                mma_f16(oacc[2 * nt16 + 0], ap, bvc[0], bvc[1]);
                mma_f16(oacc[2 * nt16 + 1], ap, bvc[2], bvc[3]);
            }
        }
        __syncthreads();
    }

    // ---- row-sum reduce within warp ----
    rp0 += __shfl_xor_sync(0xffffffffu, rp0, 1);
    rp0 += __shfl_xor_sync(0xffffffffu, rp0, 2);
    rp1 += __shfl_xor_sync(0xffffffffu, rp1, 1);
    rp1 += __shfl_xor_sync(0xffffffffu, rp1, 2);
    float inv0 = 1.f / rp0, inv1 = 1.f / rp1;

    // ---- write out (fp16) ----
    __half* obase = out + (long)(t * HW) * DIM + h * DH;
    int qr0 = qb * 128 + warp * 16 + g, qr1 = qr0 + 8;
    #pragma unroll
    for (int nt = 0; nt < 16; nt++) {
        int d = nt * 8 + 2 * t4;
        if (qr0 < HW) {
            __half2 h2v = __floats2half2_rn(oacc[nt][0] * inv0, oacc[nt][1] * inv0);
            *(unsigned*)(obase + (long)qr0 * DIM + d) = *(unsigned*)&h2v;
        }
        if (qr1 < HW) {
            __half2 h2v = __floats2half2_rn(oacc[nt][2] * inv1, oacc[nt][3] * inv1);
            *(unsigned*)(obase + (long)qr1 * DIM + d) = *(unsigned*)&h2v;
        }
    }
}

// ---------------- launch (5 sequential launches) ----------------
extern "C" void kernel_launch(void* const* d_in, const int* in_sizes, int n_in,
                              void* d_out, int out_size)
{
    const float* hidden  = (const float*)d_in[0];
    const float* history = (const float*)d_in[1];
    const float* fc   = (const float*)d_in[2];
    const float* fs   = (const float*)d_in[3];
    const float* fch  = (const float*)d_in[4];
    const float* fsh  = (const float*)d_in[5];
    const int*   sel  = (const int*)d_in[6];
    const float* Wq = (const float*)d_in[7];
    const float* bq = (const float*)d_in[8];
    const float* Wk = (const float*)d_in[9];
    const float* bk = (const float*)d_in[10];
    const float* Wv = (const float*)d_in[11];
    const float* bv = (const float*)d_in[12];
    const float* Wo = (const float*)d_in[13];
    const float* bo = (const float*)d_in[14];
    const float* gq = (const float*)d_in[15];
    const float* gk = (const float*)d_in[16];
    float* outp = (float*)d_out;

    __half *qp, *kp, *vp, *ap, *hidh, *hish, *wqh, *wkh, *wvh, *woh;
    cudaGetSymbolAddress((void**)&qp, g_q);
    cudaGetSymbolAddress((void**)&kp, g_k);
    cudaGetSymbolAddress((void**)&vp, g_v);
    cudaGetSymbolAddress((void**)&ap, g_attn);
    cudaGetSymbolAddress((void**)&hidh, g_hid);
    cudaGetSymbolAddress((void**)&hish, g_his);
    cudaGetSymbolAddress((void**)&wqh, g_wq);
    cudaGetSymbolAddress((void**)&wkh, g_wk);
    cudaGetSymbolAddress((void**)&wvh, g_wv);
    cudaGetSymbolAddress((void**)&woh, g_wo);

    cudaFuncSetAttribute(gemm_qkv,
                         cudaFuncAttributeMaxDynamicSharedMemorySize, GEMM_SMEM);
    cudaFuncSetAttribute(gemm_o,
                         cudaFuncAttributeMaxDynamicSharedMemorySize, GEMM_SMEM);
    cudaFuncSetAttribute(attention_kernel,
                         cudaFuncAttributeMaxDynamicSharedMemorySize, ATT_SMEM);

    cvt_all<<<4 * DIM + QTOT + KTOT, 192>>>(
        Wq, Wk, Wv, Wo, hidden, history,
        wqh, wkh, wvh, woh, hidh, hish, sel);

    gemm_qkv<<<dim3(12, 98, 3), 256, GEMM_SMEM>>>(
        hidh, hish, wqh, wkh, wvh, bq, bk, bv, qp, kp, vp, sel);

    rmsnorm_all<<<QTOT + KTOT, 384>>>(qp, kp, gq, gk, fc, fs, fch, fsh, sel);

    attention_kernel<<<dim3(13, TQ, HEADS), 256, ATT_SMEM>>>(qp, kp, vp, sel, ap);

    gemm_o<<<dim3(12, 25), 256, GEMM_SMEM>>>(ap, woh, bo, outp);
}

// round 16
// speedup vs baseline: 1.0054x; 1.0054x over previous
#include <cuda_runtime.h>
#include <cuda_fp16.h>
#include <cstdint>

#define HW    1560
#define TQ    2
#define QTOT  3120
#define KTOT  12480
#define HEADS 12
#define DH    128
#define DIM   1536

// ---------------- scratch (device globals; no allocation allowed) ----------------
__device__ __half g_q[QTOT * DIM];
__device__ __half g_k[KTOT * DIM];
__device__ __half g_v[KTOT * DIM];
__device__ __half g_attn[QTOT * DIM];
__device__ __half g_hid[QTOT * DIM];
__device__ __half g_his[KTOT * DIM];
__device__ __half g_wq[DIM * DIM];
__device__ __half g_wk[DIM * DIM];
__device__ __half g_wv[DIM * DIM];
__device__ __half g_wo[DIM * DIM];
// attention partials: 4 subs = (key-half, kpq)
__device__ float g_po[4ull * QTOT * DIM];      // 76.6 MB, unnormalized O partials
__device__ float g_pr[4ull * QTOT * HEADS];    // row-sum partials

// ---------------- helpers ----------------
__device__ __forceinline__ void mma_f16(float* d, const unsigned* a, unsigned b0, unsigned b1) {
    asm volatile(
        "mma.sync.aligned.m16n8k16.row.col.f32.f16.f16.f32 "
        "{%0,%1,%2,%3}, {%4,%5,%6,%7}, {%8,%9}, {%0,%1,%2,%3};"
        : "+f"(d[0]), "+f"(d[1]), "+f"(d[2]), "+f"(d[3])
        : "r"(a[0]), "r"(a[1]), "r"(a[2]), "r"(a[3]), "r"(b0), "r"(b1));
}

__device__ __forceinline__ uint32_t smem_u32(const void* p) {
    uint32_t a;
    asm("{ .reg .u64 t; cvta.to.shared.u64 t, %1; cvt.u32.u64 %0, t; }" : "=r"(a) : "l"(p));
    return a;
}

__device__ __forceinline__ void ldsm_x4(unsigned* r, uint32_t addr) {
    asm volatile("ldmatrix.sync.aligned.m8n8.x4.shared.b16 {%0,%1,%2,%3}, [%4];"
                 : "=r"(r[0]), "=r"(r[1]), "=r"(r[2]), "=r"(r[3]) : "r"(addr));
}

__device__ __forceinline__ void ldsm_x4_trans(unsigned* r, uint32_t addr) {
    asm volatile("ldmatrix.sync.aligned.m8n8.x4.trans.shared.b16 {%0,%1,%2,%3}, [%4];"
                 : "=r"(r[0]), "=r"(r[1]), "=r"(r[2]), "=r"(r[3]) : "r"(addr));
}

__device__ __forceinline__ void cp_async16(uint32_t dst, const void* src, bool valid) {
    int sz = valid ? 16 : 0;
    asm volatile("cp.async.cg.shared.global [%0], [%1], 16, %2;"
                 :: "r"(dst), "l"(src), "r"(sz) : "memory");
}
__device__ __forceinline__ void cp_commit() {
    asm volatile("cp.async.commit_group;" ::: "memory");
}
__device__ __forceinline__ void cp_wait1() {
    asm volatile("cp.async.wait_group 1;" ::: "memory");
}
__device__ __forceinline__ void cp_wait0() {
    asm volatile("cp.async.wait_group 0;" ::: "memory");
}

__device__ __forceinline__ uint2 f4_to_h4(float4 v) {
    __half2 h0 = __float22half2_rn(make_float2(v.x, v.y));
    __half2 h1 = __float22half2_rn(make_float2(v.z, v.w));
    uint2 r;
    r.x = *(unsigned*)&h0;
    r.y = *(unsigned*)&h1;
    return r;
}

__device__ __forceinline__ bool block_needed(int b, const int* __restrict__ sel) {
    return (sel[0] == b) | (sel[1] == b) | (sel[2] == b) | (sel[3] == b);
}

// ---------------- fused one-time fp32 -> fp16 conversions (single launch) ----------------
__global__ __launch_bounds__(192) void cvt_all(
    const float* __restrict__ Wq, const float* __restrict__ Wk,
    const float* __restrict__ Wv, const float* __restrict__ Wo,
    const float* __restrict__ hidden, const float* __restrict__ history,
    __half* __restrict__ wq, __half* __restrict__ wk,
    __half* __restrict__ wv, __half* __restrict__ wo,
    __half* __restrict__ hid, __half* __restrict__ his,
    const int* __restrict__ sel)
{
    int b = blockIdx.x;
    const float* src;
    __half* dst;
    long row;
    if (b < 4 * DIM) {
        if (b < DIM)          { src = Wq; dst = wq; row = b; }
        else if (b < 2 * DIM) { src = Wk; dst = wk; row = b - DIM; }
        else if (b < 3 * DIM) { src = Wv; dst = wv; row = b - 2 * DIM; }
        else                  { src = Wo; dst = wo; row = b - 3 * DIM; }
    } else if (b < 4 * DIM + QTOT) {
        src = hidden; dst = hid; row = b - 4 * DIM;
    } else {
        row = b - (4 * DIM + QTOT);
        if (!block_needed((int)(row / HW), sel)) return;
        src = history; dst = his;
    }
    const int c = threadIdx.x * 8;
    const float* s = src + row * DIM + c;
    float4 f0 = *(const float4*)s;
    float4 f1 = *(const float4*)(s + 4);
    uint2 h0 = f4_to_h4(f0), h1 = f4_to_h4(f1);
    *(uint4*)(dst + row * DIM + c) = make_uint4(h0.x, h0.y, h1.x, h1.y);
}

// ---------------- GEMM core (unchanged) ----------------
#define GEMM_STAGE_H (128 * 40)
#define GEMM_SMEM    (2 * 2 * GEMM_STAGE_H * 2)   // 40960 bytes

template <bool OUT_HALF>
__device__ __forceinline__ void gemm_core(
    const __half* __restrict__ A, const __half* __restrict__ W,
    const float* __restrict__ bias, void* __restrict__ Cv,
    int M, int N, int K, const int* __restrict__ sel)
{
    extern __shared__ __half gh[];
    float*  Cf = (float*)Cv;
    __half* Ch = (__half*)Cv;

    const int bm = blockIdx.y * 128, bn = blockIdx.x * 128;

    if (sel) {
        int b0 = bm / HW;
        int b1 = (bm + 127) / HW;
        if (!block_needed(b0, sel) && !block_needed(b1, sel)) return;
    }

    const int tid  = threadIdx.x;
    const int warp = tid >> 5, lane = tid & 31;
    const int g = lane >> 2, t4 = lane & 3;
    const int wm = warp >> 2, wn = warp & 3;

    float acc[4][4][4] = {};

    const int lc2 = (tid & 3) * 8;
    const int lr2 = tid >> 2;

    const int i8 = lane >> 3, r8 = lane & 7;
    const int a_row = (i8 & 1) * 8 + r8;
    const int a_ko  = (i8 >> 1) * 8;
    const uint32_t gh_b = smem_u32(gh);
    uint32_t aoff[4], boff[2];
    #pragma unroll
    for (int mt = 0; mt < 4; mt++)
        aoff[mt] = ((wm * 64 + mt * 16 + a_row) * 40 + a_ko) * 2;
    #pragma unroll
    for (int np = 0; np < 2; np++) {
        int b_row = (i8 >> 1) * 8 + r8;
        int b_ko  = (i8 & 1) * 8;
        boff[np] = ((wn * 32 + np * 16 + b_row) * 40 + b_ko) * 2;
    }

    uint4 aH[2], wH[2];
    const uint4 z4 = make_uint4(0u, 0u, 0u, 0u);

    #pragma unroll
    for (int i = 0; i < 2; i++) {
        int row = lr2 + 64 * i;
        long ar = bm + row;
        aH[i] = (ar < M) ? *(const uint4*)(A + ar * (long)K + lc2) : z4;
        wH[i] = *(const uint4*)(W + (long)(bn + row) * K + lc2);
    }

    {
        __half* As = gh;
        __half* Ws = gh + GEMM_STAGE_H;
        #pragma unroll
        for (int i = 0; i < 2; i++) {
            int row = lr2 + 64 * i;
            *(uint4*)&As[row * 40 + lc2] = aH[i];
            *(uint4*)&Ws[row * 40 + lc2] = wH[i];
        }
    }
    __syncthreads();

    const int KT = K >> 5;
    for (int kt = 0; kt < KT; kt++) {
        const uint32_t As_b = gh_b + (kt & 1) * (4 * GEMM_STAGE_H);
        const uint32_t Ws_b = As_b + 2 * GEMM_STAGE_H;

        if (kt + 1 < KT) {
            int k0 = (kt + 1) << 5;
            #pragma unroll
            for (int i = 0; i < 2; i++) {
                int row = lr2 + 64 * i;
                long ar = bm + row;
                aH[i] = (ar < M) ? *(const uint4*)(A + ar * (long)K + k0 + lc2) : z4;
                wH[i] = *(const uint4*)(W + (long)(bn + row) * K + k0 + lc2);
            }
        }

        #pragma unroll
        for (int kk = 0; kk < 2; kk++) {
            const uint32_t kB = kk * 32;
            unsigned a[4][4], b[2][4];
            #pragma unroll
            for (int mt = 0; mt < 4; mt++) ldsm_x4(a[mt], As_b + aoff[mt] + kB);
            #pragma unroll
            for (int np = 0; np < 2; np++) ldsm_x4(b[np], Ws_b + boff[np] + kB);
            #pragma unroll
            for (int nt = 0; nt < 4; nt++) {
                unsigned b0 = b[nt >> 1][(nt & 1) * 2];
                unsigned b1 = b[nt >> 1][(nt & 1) * 2 + 1];
                #pragma unroll
                for (int mt = 0; mt < 4; mt++)
                    mma_f16(acc[mt][nt], a[mt], b0, b1);
            }
        }

        if (kt + 1 < KT) {
            __half* Asn = gh + ((kt + 1) & 1) * 2 * GEMM_STAGE_H;
            __half* Wsn = Asn + GEMM_STAGE_H;
            #pragma unroll
            for (int i = 0; i < 2; i++) {
                int row = lr2 + 64 * i;
                *(uint4*)&Asn[row * 40 + lc2] = aH[i];
                *(uint4*)&Wsn[row * 40 + lc2] = wH[i];
            }
        }
        __syncthreads();
    }

    #pragma unroll
    for (int mt = 0; mt < 4; mt++) {
        int r = bm + wm * 64 + mt * 16 + g;
        #pragma unroll
        for (int nt = 0; nt < 4; nt++) {
            int c = bn + wn * 32 + nt * 8 + t4 * 2;
            float b0 = bias[c], b1 = bias[c + 1];
            if (OUT_HALF) {
                if (r < M) {
                    __half2 h = __floats2half2_rn(acc[mt][nt][0] + b0, acc[mt][nt][1] + b1);
                    *(unsigned*)(Ch + (long)r * N + c) = *(unsigned*)&h;
                }
                if (r + 8 < M) {
                    __half2 h = __floats2half2_rn(acc[mt][nt][2] + b0, acc[mt][nt][3] + b1);
                    *(unsigned*)(Ch + (long)(r + 8) * N + c) = *(unsigned*)&h;
                }
            } else {
                if (r < M)
                    *(float2*)(Cf + (long)r * N + c) =
                        make_float2(acc[mt][nt][0] + b0, acc[mt][nt][1] + b1);
                if (r + 8 < M)
                    *(float2*)(Cf + (long)(r + 8) * N + c) =
                        make_float2(acc[mt][nt][2] + b0, acc[mt][nt][3] + b1);
            }
        }
    }
}

__global__ __launch_bounds__(256, 2) void gemm_qkv(
    const __half* __restrict__ hid, const __half* __restrict__ his,
    const __half* __restrict__ wq, const __half* __restrict__ wk,
    const __half* __restrict__ wv,
    const float* __restrict__ bq, const float* __restrict__ bk,
    const float* __restrict__ bv,
    __half* __restrict__ q, __half* __restrict__ k, __half* __restrict__ v,
    const int* __restrict__ sel)
{
    const int z = blockIdx.z;
    if (z == 0) {
        if (blockIdx.y >= 25) return;
        gemm_core<true>(hid, wq, bq, q, QTOT, DIM, DIM, nullptr);
    } else if (z == 1) {
        gemm_core<true>(his, wk, bk, k, KTOT, DIM, DIM, sel);
    } else {
        gemm_core<true>(his, wv, bv, v, KTOT, DIM, DIM, sel);
    }
}

__global__ __launch_bounds__(256, 2) void gemm_o(
    const __half* __restrict__ A, const __half* __restrict__ W,
    const float* __restrict__ bias, float* __restrict__ C)
{
    gemm_core<false>(A, W, bias, C, QTOT, DIM, DIM, nullptr);
}

// ---------------- fused RMSNorm + RoPE for q AND k in one launch ----------------
__global__ __launch_bounds__(384) void rmsnorm_all(
    __half* __restrict__ q, __half* __restrict__ k,
    const float* __restrict__ gq, const float* __restrict__ gk,
    const float* __restrict__ fc, const float* __restrict__ fs,
    const float* __restrict__ fch, const float* __restrict__ fsh,
    const int* __restrict__ sel)
{
    __shared__ float red[12];
    __shared__ float rinv_s;
    int row = blockIdx.x;
    const int tid = threadIdx.x;

    __half* x;
    const float *gamma, *fcp, *fsp;
    if (row < QTOT) {
        x = q; gamma = gq; fcp = fc; fsp = fs;
    } else {
        row -= QTOT;
        if (!block_needed(row / HW, sel)) return;
        x = k; gamma = gk; fcp = fch; fsp = fsh;
    }

    uint2 u = *(uint2*)(x + (long)row * DIM + tid * 4);
    __half2 h01 = *(__half2*)&u.x;
    __half2 h23 = *(__half2*)&u.y;
    float2 f01 = __half22float2(h01);
    float2 f23 = __half22float2(h23);

    float ss = f01.x * f01.x + f01.y * f01.y + f23.x * f23.x + f23.y * f23.y;
    #pragma unroll
    for (int s = 16; s > 0; s >>= 1) ss += __shfl_xor_sync(0xffffffffu, ss, s);
    if ((tid & 31) == 0) red[tid >> 5] = ss;
    __syncthreads();
    if (tid < 32) {
        float t = (tid < 12) ? red[tid] : 0.f;
        #pragma unroll
        for (int s = 16; s > 0; s >>= 1) t += __shfl_xor_sync(0xffffffffu, t, s);
        if (tid == 0) rinv_s = rsqrtf(t * (1.0f / DIM) + 1e-5f);
    }
    __syncthreads();
    float r = rinv_s;

    float4 g4 = *(const float4*)(gamma + tid * 4);
    float x0 = f01.x * r * g4.x, x1 = f01.y * r * g4.y;
    float x2 = f23.x * r * g4.z, x3 = f23.y * r * g4.w;

    int hd = (tid * 4) & (DH - 1);
    float4 c4 = *(const float4*)(fcp + (long)row * DH + hd);
    float4 s4 = *(const float4*)(fsp + (long)row * DH + hd);
    float o0 = x0 * c4.x - x1 * s4.y;
    float o1 = x0 * s4.y + x1 * c4.x;
    float o2 = x2 * c4.z - x3 * s4.w;
    float o3 = x2 * s4.w + x3 * c4.z;

    __half2 ho01 = __floats2half2_rn(o0, o1);
    __half2 ho23 = __floats2half2_rn(o2, o3);
    *(uint2*)(x + (long)row * DIM + tid * 4) =
        make_uint2(*(unsigned*)&ho01, *(unsigned*)&ho23);
}

// ---------------- block-sparse attention, split into 4 sub-items per (qb,t,h) ----------------
// grid (13, 8, 12): y = t*4 + sub, sub = half*2 + kpq.
// Each CTA handles ONE selected k-block (kpq) and ONE key-half (13 or 12 tiles),
// writing unnormalized O and row-sum partials. Combine kernel normalizes.
#define AQ_OFF   0
#define AK_OFF   34816
#define KV_STAGE 17408
#define AV_OFF   (AK_OFF + 2 * KV_STAGE)
#define ATT_SMEM (AV_OFF + 2 * KV_STAGE)   // 104448

__global__ __launch_bounds__(256, 2) void attention_kernel(
    const __half* __restrict__ q, const __half* __restrict__ k,
    const __half* __restrict__ v, const int* __restrict__ sel,
    float* __restrict__ po, float* __restrict__ pr)
{
    const int qb = blockIdx.x, h = blockIdx.z;
    const int t = blockIdx.y >> 2, sub = blockIdx.y & 3;
    const int kpq = sub & 1, half = sub >> 1;

    int blk = sel[t * 2 + kpq];
    if (blk < 0) return;                 // only kpq=1 can be invalid

    extern __shared__ char asm_[];
    __half* Qh = (__half*)(asm_ + AQ_OFF);

    const int tid = threadIdx.x, warp = tid >> 5, lane = tid & 31;
    const int g = lane >> 2, t4 = lane & 3;

    const int i8 = lane >> 3, r8 = lane & 7;
    const uint32_t smb = smem_u32(asm_);
    const uint32_t qoff = smb + ((warp * 16 + (i8 & 1) * 8 + r8) * 136 + (i8 >> 1) * 8) * 2;
    uint32_t koff_l[4];
    #pragma unroll
    for (int np = 0; np < 4; np++)
        koff_l[np] = ((np * 16 + (i8 >> 1) * 8 + r8) * 136 + (i8 & 1) * 8) * 2;
    const uint32_t voff_l = (((i8 & 1) * 8 + r8) * 136 + (i8 >> 1) * 8) * 2;

    const uint4 z4 = make_uint4(0u, 0u, 0u, 0u);

    // load Q tile (fp16, zero-fill tail rows)
    const __half* qbase = q + (long)(t * HW) * DIM + (long)h * DH;
    {
        const int c8 = (tid & 15) * 8;
        const int lr0q = tid >> 4;
        #pragma unroll
        for (int i = 0; i < 8; i++) {
            int r = lr0q + i * 16;
            int qr = qb * 128 + r;
            uint4 val = (qr < HW) ? *(const uint4*)(qbase + (long)qr * DIM + c8) : z4;
            *(uint4*)&Qh[r * 136 + c8] = val;
        }
    }

    float oacc[16][4] = {};
    float rp0 = 0.f, rp1 = 0.f;

    const __half* kbp = k + (long)blk * HW * DIM + (long)h * DH;
    const __half* vbp = v + (long)blk * HW * DIM + (long)h * DH;

    const int tstart = half ? 13 : 0;
    const int ntile  = half ? 12 : 13;   // keys [tstart*64, ...) masked at HW

    const int lc8 = (tid & 15) * 8;
    const int lr0 = tid >> 4;

    auto issue_tile = [&](int ti) {      // ti = 0..ntile-1 (local)
        int n0 = (tstart + ti) * 64;
        uint32_t kdst = smb + AK_OFF + (ti & 1) * KV_STAGE;
        uint32_t vdst = smb + AV_OFF + (ti & 1) * KV_STAGE;
        #pragma unroll
        for (int i = 0; i < 4; i++) {
            int r = lr0 + i * 16;
            int kr = n0 + r;
            bool valid = kr < HW;
            long off = valid ? ((long)kr * DIM + lc8) : 0;
            uint32_t d = (r * 136 + lc8) * 2;
            cp_async16(kdst + d, kbp + off, valid);
            cp_async16(vdst + d, vbp + off, valid);
        }
        cp_commit();
    };

    __syncthreads();
    issue_tile(0);

    const float SC   = 0.08838834764831843f * 1.4426950408889634f;
    const float OFFL = 4.0f * 1.4426950408889634f;

    for (int ti = 0; ti < ntile; ti++) {
        if (ti + 1 < ntile) { issue_tile(ti + 1); cp_wait1(); }
        else                { cp_wait0(); }
        __syncthreads();

        const uint32_t Kb = smb + AK_OFF + (ti & 1) * KV_STAGE;
        const uint32_t Vb = smb + AV_OFF + (ti & 1) * KV_STAGE;
        const int n0 = (tstart + ti) * 64;

        // ---- QK^T via ldmatrix ----
        float sacc[8][4] = {};
        #pragma unroll
        for (int ks = 0; ks < 8; ks++) {
            const uint32_t kB = ks * 32;
            unsigned a[4], b[4][4];
            ldsm_x4(a, qoff + kB);
            #pragma unroll
            for (int np = 0; np < 4; np++) ldsm_x4(b[np], Kb + koff_l[np] + kB);
            #pragma unroll
            for (int nt = 0; nt < 8; nt++) {
                unsigned b0 = b[nt >> 1][(nt & 1) * 2];
                unsigned b1 = b[nt >> 1][(nt & 1) * 2 + 1];
                mma_f16(sacc[nt], a, b0, b1);
            }
        }

        // ---- softmax numerators; P fragments = PV A-fragments ----
        unsigned ap[4][4];
        #pragma unroll
        for (int nt = 0; nt < 8; nt++) {
            int cn = nt * 8 + 2 * t4;
            bool m0 = (n0 + cn) < HW, m1 = (n0 + cn + 1) < HW;
            float p0 = m0 ? exp2f(fmaf(sacc[nt][0], SC, -OFFL)) : 0.f;
            float p1 = m1 ? exp2f(fmaf(sacc[nt][1], SC, -OFFL)) : 0.f;
            float p2 = m0 ? exp2f(fmaf(sacc[nt][2], SC, -OFFL)) : 0.f;
            float p3 = m1 ? exp2f(fmaf(sacc[nt][3], SC, -OFFL)) : 0.f;
            rp0 += p0 + p1;
            rp1 += p2 + p3;
            __half2 h01 = __floats2half2_rn(p0, p1);
            __half2 h23 = __floats2half2_rn(p2, p3);
            ap[nt >> 1][(nt & 1) * 2 + 0] = *(unsigned*)&h01;
            ap[nt >> 1][(nt & 1) * 2 + 1] = *(unsigned*)&h23;
        }

        // ---- P @ V via ldmatrix.trans ----
        #pragma unroll
        for (int kp = 0; kp < 4; kp++) {
            const uint32_t kbase = Vb + voff_l + kp * (16 * 136 * 2);
            #pragma unroll
            for (int nt16 = 0; nt16 < 8; nt16++) {
                unsigned bv[4];
                ldsm_x4_trans(bv, kbase + nt16 * 32);
                mma_f16(oacc[2 * nt16 + 0], ap[kp], bv[0], bv[1]);
                mma_f16(oacc[2 * nt16 + 1], ap[kp], bv[2], bv[3]);
            }
        }
        __syncthreads();
    }

    // ---- reduce row sums within warp ----
    rp0 += __shfl_xor_sync(0xffffffffu, rp0, 1);
    rp0 += __shfl_xor_sync(0xffffffffu, rp0, 2);
    rp1 += __shfl_xor_sync(0xffffffffu, rp1, 1);
    rp1 += __shfl_xor_sync(0xffffffffu, rp1, 2);

    // ---- write unnormalized partials ----
    int qr0 = qb * 128 + warp * 16 + g, qr1 = qr0 + 8;
    long row0 = (long)sub * QTOT + t * HW + qr0;
    long row1 = row0 + 8;
    if (t4 == 0) {
        if (qr0 < HW) pr[row0 * HEADS + h] = rp0;
        if (qr1 < HW) pr[row1 * HEADS + h] = rp1;
    }
    float* pbase = po + (long)h * DH;
    #pragma unroll
    for (int nt = 0; nt < 16; nt++) {
        int d = nt * 8 + 2 * t4;
        if (qr0 < HW)
            *(float2*)(pbase + row0 * DIM + d) = make_float2(oacc[nt][0], oacc[nt][1]);
        if (qr1 < HW)
            *(float2*)(pbase + row1 * DIM + d) = make_float2(oacc[nt][2], oacc[nt][3]);
    }
}

// ---------------- combine partials: out = (sum O) / (sum r) ----------------
__global__ __launch_bounds__(384) void att_combine(
    const float* __restrict__ po, const float* __restrict__ pr,
    const int* __restrict__ sel, __half* __restrict__ out)
{
    const int row = blockIdx.x;          // 0..QTOT-1
    const int t = row / HW;
    const int c = threadIdx.x * 4;
    const int h = c >> 7;                // /DH
    const bool v1 = sel[t * 2 + 1] >= 0;

    float4 o = make_float4(0.f, 0.f, 0.f, 0.f);
    float r = 0.f;
    #pragma unroll
    for (int sub = 0; sub < 4; sub++) {
        if ((sub & 1) && !v1) continue;
        long prow = (long)sub * QTOT + row;
        float4 x = *(const float4*)(po + prow * DIM + c);
        o.x += x.x; o.y += x.y; o.z += x.z; o.w += x.w;
        r += pr[prow * HEADS + h];
    }
    float inv = 1.f / r;
    __half2 h01 = __floats2half2_rn(o.x * inv, o.y * inv);
    __half2 h23 = __floats2half2_rn(o.z * inv, o.w * inv);
    *(uint2*)(out + (long)row * DIM + c) =
        make_uint2(*(unsigned*)&h01, *(unsigned*)&h23);
}

// ---------------- launch (6 sequential launches) ----------------
extern "C" void kernel_launch(void* const* d_in, const int* in_sizes, int n_in,
                              void* d_out, int out_size)
{
    const float* hidden  = (const float*)d_in[0];
    const float* history = (const float*)d_in[1];
    const float* fc   = (const float*)d_in[2];
    const float* fs   = (const float*)d_in[3];
    const float* fch  = (const float*)d_in[4];
    const float* fsh  = (const float*)d_in[5];
    const int*   sel  = (const int*)d_in[6];
    const float* Wq = (const float*)d_in[7];
    const float* bq = (const float*)d_in[8];
    const float* Wk = (const float*)d_in[9];
    const float* bk = (const float*)d_in[10];
    const float* Wv = (const float*)d_in[11];
    const float* bv = (const float*)d_in[12];
    const float* Wo = (const float*)d_in[13];
    const float* bo = (const float*)d_in[14];
    const float* gq = (const float*)d_in[15];
    const float* gk = (const float*)d_in[16];
    float* outp = (float*)d_out;

    __half *qp, *kp, *vp, *ap, *hidh, *hish, *wqh, *wkh, *wvh, *woh;
    float *pop, *prp;
    cudaGetSymbolAddress((void**)&qp, g_q);
    cudaGetSymbolAddress((void**)&kp, g_k);
    cudaGetSymbolAddress((void**)&vp, g_v);
    cudaGetSymbolAddress((void**)&ap, g_attn);
    cudaGetSymbolAddress((void**)&hidh, g_hid);
    cudaGetSymbolAddress((void**)&hish, g_his);
    cudaGetSymbolAddress((void**)&wqh, g_wq);
    cudaGetSymbolAddress((void**)&wkh, g_wk);
    cudaGetSymbolAddress((void**)&wvh, g_wv);
    cudaGetSymbolAddress((void**)&woh, g_wo);
    cudaGetSymbolAddress((void**)&pop, g_po);
    cudaGetSymbolAddress((void**)&prp, g_pr);

    cudaFuncSetAttribute(gemm_qkv,
                         cudaFuncAttributeMaxDynamicSharedMemorySize, GEMM_SMEM);
    cudaFuncSetAttribute(gemm_o,
                         cudaFuncAttributeMaxDynamicSharedMemorySize, GEMM_SMEM);
    cudaFuncSetAttribute(attention_kernel,
                         cudaFuncAttributeMaxDynamicSharedMemorySize, ATT_SMEM);

    cvt_all<<<4 * DIM + QTOT + KTOT, 192>>>(
        Wq, Wk, Wv, Wo, hidden, history,
        wqh, wkh, wvh, woh, hidh, hish, sel);

    gemm_qkv<<<dim3(12, 98, 3), 256, GEMM_SMEM>>>(
        hidh, hish, wqh, wkh, wvh, bq, bk, bv, qp, kp, vp, sel);

    rmsnorm_all<<<QTOT + KTOT, 384>>>(qp, kp, gq, gk, fc, fs, fch, fsh, sel);

    attention_kernel<<<dim3(13, TQ * 4, HEADS), 256, ATT_SMEM>>>(qp, kp, vp, sel, pop, prp);

    att_combine<<<QTOT, 384>>>(pop, prp, sel, ap);

    gemm_o<<<dim3(12, 25), 256, GEMM_SMEM>>>(ap, woh, bo, outp);
}

// round 17
// speedup vs baseline: 1.0223x; 1.0167x over previous
#include <cuda_runtime.h>
#include <cuda_fp16.h>
#include <cstdint>

#define HW    1560
#define TQ    2
#define QTOT  3120
#define KTOT  12480
#define HEADS 12
#define DH    128
#define DIM   1536

// ---------------- scratch (device globals; no allocation allowed) ----------------
__device__ __half g_q[QTOT * DIM];
__device__ __half g_k[KTOT * DIM];
__device__ __half g_v[KTOT * DIM];
__device__ __half g_attn[QTOT * DIM];
__device__ __half g_hid[QTOT * DIM];
__device__ __half g_his[KTOT * DIM];
__device__ __half g_wq[DIM * DIM];
__device__ __half g_wk[DIM * DIM];
__device__ __half g_wv[DIM * DIM];
__device__ __half g_wo[DIM * DIM];
// attention partials: 4 subs = (key-half, kpq)
__device__ float g_po[4ull * QTOT * DIM];
__device__ float g_pr[4ull * QTOT * HEADS];

// ---------------- helpers ----------------
__device__ __forceinline__ void mma_f16(float* d, const unsigned* a, unsigned b0, unsigned b1) {
    asm volatile(
        "mma.sync.aligned.m16n8k16.row.col.f32.f16.f16.f32 "
        "{%0,%1,%2,%3}, {%4,%5,%6,%7}, {%8,%9}, {%0,%1,%2,%3};"
        : "+f"(d[0]), "+f"(d[1]), "+f"(d[2]), "+f"(d[3])
        : "r"(a[0]), "r"(a[1]), "r"(a[2]), "r"(a[3]), "r"(b0), "r"(b1));
}

__device__ __forceinline__ uint32_t smem_u32(const void* p) {
    uint32_t a;
    asm("{ .reg .u64 t; cvta.to.shared.u64 t, %1; cvt.u32.u64 %0, t; }" : "=r"(a) : "l"(p));
    return a;
}

__device__ __forceinline__ void ldsm_x4(unsigned* r, uint32_t addr) {
    asm volatile("ldmatrix.sync.aligned.m8n8.x4.shared.b16 {%0,%1,%2,%3}, [%4];"
                 : "=r"(r[0]), "=r"(r[1]), "=r"(r[2]), "=r"(r[3]) : "r"(addr));
}

__device__ __forceinline__ void ldsm_x4_trans(unsigned* r, uint32_t addr) {
    asm volatile("ldmatrix.sync.aligned.m8n8.x4.trans.shared.b16 {%0,%1,%2,%3}, [%4];"
                 : "=r"(r[0]), "=r"(r[1]), "=r"(r[2]), "=r"(r[3]) : "r"(addr));
}

__device__ __forceinline__ void cp_async16(uint32_t dst, const void* src, bool valid) {
    int sz = valid ? 16 : 0;
    asm volatile("cp.async.cg.shared.global [%0], [%1], 16, %2;"
                 :: "r"(dst), "l"(src), "r"(sz) : "memory");
}
__device__ __forceinline__ void cp_commit() {
    asm volatile("cp.async.commit_group;" ::: "memory");
}
__device__ __forceinline__ void cp_wait1() {
    asm volatile("cp.async.wait_group 1;" ::: "memory");
}
__device__ __forceinline__ void cp_wait0() {
    asm volatile("cp.async.wait_group 0;" ::: "memory");
}

__device__ __forceinline__ uint2 f4_to_h4(float4 v) {
    __half2 h0 = __float22half2_rn(make_float2(v.x, v.y));
    __half2 h1 = __float22half2_rn(make_float2(v.z, v.w));
    uint2 r;
    r.x = *(unsigned*)&h0;
    r.y = *(unsigned*)&h1;
    return r;
}

__device__ __forceinline__ bool block_needed(int b, const int* __restrict__ sel) {
    return (sel[0] == b) | (sel[1] == b) | (sel[2] == b) | (sel[3] == b);
}

// ---------------- fused one-time fp32 -> fp16 conversions (single launch) ----------------
__global__ __launch_bounds__(192) void cvt_all(
    const float* __restrict__ Wq, const float* __restrict__ Wk,
    const float* __restrict__ Wv, const float* __restrict__ Wo,
    const float* __restrict__ hidden, const float* __restrict__ history,
    __half* __restrict__ wq, __half* __restrict__ wk,
    __half* __restrict__ wv, __half* __restrict__ wo,
    __half* __restrict__ hid, __half* __restrict__ his,
    const int* __restrict__ sel)
{
    int b = blockIdx.x;
    const float* src;
    __half* dst;
    long row;
    if (b < 4 * DIM) {
        if (b < DIM)          { src = Wq; dst = wq; row = b; }
        else if (b < 2 * DIM) { src = Wk; dst = wk; row = b - DIM; }
        else if (b < 3 * DIM) { src = Wv; dst = wv; row = b - 2 * DIM; }
        else                  { src = Wo; dst = wo; row = b - 3 * DIM; }
    } else if (b < 4 * DIM + QTOT) {
        src = hidden; dst = hid; row = b - 4 * DIM;
    } else {
        row = b - (4 * DIM + QTOT);
        if (!block_needed((int)(row / HW), sel)) return;
        src = history; dst = his;
    }
    const int c = threadIdx.x * 8;
    const float* s = src + row * DIM + c;
    float4 f0 = *(const float4*)s;
    float4 f1 = *(const float4*)(s + 4);
    uint2 h0 = f4_to_h4(f0), h1 = f4_to_h4(f1);
    *(uint4*)(dst + row * DIM + c) = make_uint4(h0.x, h0.y, h1.x, h1.y);
}

// ---------------- GEMM core: cp.async 3-stage pipeline, 1 sync per k-tile ----------------
// block tile 128x128x32, 256 threads = 8 warps (2M x 4N), warp tile 64x32, ldmatrix frags.
#define GST_H    (128 * 40)                // halves per matrix per stage (row stride 40)
#define GST_W    (GST_H * 2)               // byte offset of W region within a stage
#define GST_B    (2 * GST_H * 2)           // stage bytes = 20480
#define NST      3
#define GEMM_SMEM (NST * GST_B)            // 61440

template <bool OUT_HALF>
__device__ __forceinline__ void gemm_core(
    const __half* __restrict__ A, const __half* __restrict__ W,
    const float* __restrict__ bias, void* __restrict__ Cv,
    int M, int N, int K, const int* __restrict__ sel)
{
    extern __shared__ __half gh[];
    float*  Cf = (float*)Cv;
    __half* Ch = (__half*)Cv;

    const int bm = blockIdx.y * 128, bn = blockIdx.x * 128;

    if (sel) {
        int b0 = bm / HW;
        int b1 = (bm + 127) / HW;
        if (!block_needed(b0, sel) && !block_needed(b1, sel)) return;
    }

    const int tid  = threadIdx.x;
    const int warp = tid >> 5, lane = tid & 31;
    const int g = lane >> 2, t4 = lane & 3;
    const int wm = warp >> 2, wn = warp & 3;

    float acc[4][4][4] = {};

    // producer mapping: 16B = 8 halves; rows lr2, lr2+64; col lc2
    const int lc2 = (tid & 3) * 8;
    const int lr2 = tid >> 2;
    const bool av0 = (bm + lr2) < M;
    const bool av1 = (bm + lr2 + 64) < M;
    const __half* asrc0 = A + (size_t)(av0 ? bm + lr2 : 0) * K + lc2;
    const __half* asrc1 = A + (size_t)(av1 ? bm + lr2 + 64 : 0) * K + lc2;
    const __half* wsrc0 = W + (size_t)(bn + lr2) * K + lc2;
    const __half* wsrc1 = W + (size_t)(bn + lr2 + 64) * K + lc2;
    const uint32_t smb = smem_u32(gh);
    const uint32_t d0 = (lr2 * 40 + lc2) * 2;
    const uint32_t d1 = ((lr2 + 64) * 40 + lc2) * 2;

    // ldmatrix per-lane addressing
    const int i8 = lane >> 3, r8 = lane & 7;
    const int a_row = (i8 & 1) * 8 + r8;
    const int a_ko  = (i8 >> 1) * 8;
    uint32_t aoff[4], boff[2];
    #pragma unroll
    for (int mt = 0; mt < 4; mt++)
        aoff[mt] = ((wm * 64 + mt * 16 + a_row) * 40 + a_ko) * 2;
    #pragma unroll
    for (int np = 0; np < 2; np++) {
        int b_row = (i8 >> 1) * 8 + r8;
        int b_ko  = (i8 & 1) * 8;
        boff[np] = GST_W + ((wn * 32 + np * 16 + b_row) * 40 + b_ko) * 2;
    }

    const int KT = K >> 5;

    auto issue = [&](int kt) {
        uint32_t st = smb + (kt % NST) * GST_B;
        int k0 = kt << 5;
        cp_async16(st + d0,         asrc0 + k0, av0);
        cp_async16(st + d1,         asrc1 + k0, av1);
        cp_async16(st + GST_W + d0, wsrc0 + k0, true);
        cp_async16(st + GST_W + d1, wsrc1 + k0, true);
        cp_commit();
    };

    issue(0);
    if (KT > 1) issue(1);

    for (int kt = 0; kt < KT; kt++) {
        if (kt + 1 < KT) cp_wait1(); else cp_wait0();
        __syncthreads();                 // tile kt visible; compute(kt-1) done everywhere
        if (kt + 2 < KT) issue(kt + 2);  // into buffer freed by compute(kt-1)

        const uint32_t st = smb + (kt % NST) * GST_B;
        #pragma unroll
        for (int kk = 0; kk < 2; kk++) {
            const uint32_t kB = kk * 32;
            unsigned a[4][4], b[2][4];
            #pragma unroll
            for (int mt = 0; mt < 4; mt++) ldsm_x4(a[mt], st + aoff[mt] + kB);
            #pragma unroll
            for (int np = 0; np < 2; np++) ldsm_x4(b[np], st + boff[np] + kB);
            #pragma unroll
            for (int nt = 0; nt < 4; nt++) {
                unsigned b0 = b[nt >> 1][(nt & 1) * 2];
                unsigned b1 = b[nt >> 1][(nt & 1) * 2 + 1];
                #pragma unroll
                for (int mt = 0; mt < 4; mt++)
                    mma_f16(acc[mt][nt], a[mt], b0, b1);
            }
        }
    }

    #pragma unroll
    for (int mt = 0; mt < 4; mt++) {
        int r = bm + wm * 64 + mt * 16 + g;
        #pragma unroll
        for (int nt = 0; nt < 4; nt++) {
            int c = bn + wn * 32 + nt * 8 + t4 * 2;
            float b0 = bias[c], b1 = bias[c + 1];
            if (OUT_HALF) {
                if (r < M) {
                    __half2 h = __floats2half2_rn(acc[mt][nt][0] + b0, acc[mt][nt][1] + b1);
                    *(unsigned*)(Ch + (long)r * N + c) = *(unsigned*)&h;
                }
                if (r + 8 < M) {
                    __half2 h = __floats2half2_rn(acc[mt][nt][2] + b0, acc[mt][nt][3] + b1);
                    *(unsigned*)(Ch + (long)(r + 8) * N + c) = *(unsigned*)&h;
                }
            } else {
                if (r < M)
                    *(float2*)(Cf + (long)r * N + c) =
                        make_float2(acc[mt][nt][0] + b0, acc[mt][nt][1] + b1);
                if (r + 8 < M)
                    *(float2*)(Cf + (long)(r + 8) * N + c) =
                        make_float2(acc[mt][nt][2] + b0, acc[mt][nt][3] + b1);
            }
        }
    }
}

__global__ __launch_bounds__(256, 2) void gemm_qkv(
    const __half* __restrict__ hid, const __half* __restrict__ his,
    const __half* __restrict__ wq, const __half* __restrict__ wk,
    const __half* __restrict__ wv,
    const float* __restrict__ bq, const float* __restrict__ bk,
    const float* __restrict__ bv,
    __half* __restrict__ q, __half* __restrict__ k, __half* __restrict__ v,
    const int* __restrict__ sel)
{
    const int z = blockIdx.z;
    if (z == 0) {
        if (blockIdx.y >= 25) return;
        gemm_core<true>(hid, wq, bq, q, QTOT, DIM, DIM, nullptr);
    } else if (z == 1) {
        gemm_core<true>(his, wk, bk, k, KTOT, DIM, DIM, sel);
    } else {
        gemm_core<true>(his, wv, bv, v, KTOT, DIM, DIM, sel);
    }
}

__global__ __launch_bounds__(256, 2) void gemm_o(
    const __half* __restrict__ A, const __half* __restrict__ W,
    const float* __restrict__ bias, float* __restrict__ C)
{
    gemm_core<false>(A, W, bias, C, QTOT, DIM, DIM, nullptr);
}

// ---------------- fused RMSNorm + RoPE for q AND k in one launch ----------------
__global__ __launch_bounds__(384) void rmsnorm_all(
    __half* __restrict__ q, __half* __restrict__ k,
    const float* __restrict__ gq, const float* __restrict__ gk,
    const float* __restrict__ fc, const float* __restrict__ fs,
    const float* __restrict__ fch, const float* __restrict__ fsh,
    const int* __restrict__ sel)
{
    __shared__ float red[12];
    __shared__ float rinv_s;
    int row = blockIdx.x;
    const int tid = threadIdx.x;

    __half* x;
    const float *gamma, *fcp, *fsp;
    if (row < QTOT) {
        x = q; gamma = gq; fcp = fc; fsp = fs;
    } else {
        row -= QTOT;
        if (!block_needed(row / HW, sel)) return;
        x = k; gamma = gk; fcp = fch; fsp = fsh;
    }

    uint2 u = *(uint2*)(x + (long)row * DIM + tid * 4);
    __half2 h01 = *(__half2*)&u.x;
    __half2 h23 = *(__half2*)&u.y;
    float2 f01 = __half22float2(h01);
    float2 f23 = __half22float2(h23);

    float ss = f01.x * f01.x + f01.y * f01.y + f23.x * f23.x + f23.y * f23.y;
    #pragma unroll
    for (int s = 16; s > 0; s >>= 1) ss += __shfl_xor_sync(0xffffffffu, ss, s);
    if ((tid & 31) == 0) red[tid >> 5] = ss;
    __syncthreads();
    if (tid < 32) {
        float t = (tid < 12) ? red[tid] : 0.f;
        #pragma unroll
        for (int s = 16; s > 0; s >>= 1) t += __shfl_xor_sync(0xffffffffu, t, s);
        if (tid == 0) rinv_s = rsqrtf(t * (1.0f / DIM) + 1e-5f);
    }
    __syncthreads();
    float r = rinv_s;

    float4 g4 = *(const float4*)(gamma + tid * 4);
    float x0 = f01.x * r * g4.x, x1 = f01.y * r * g4.y;
    float x2 = f23.x * r * g4.z, x3 = f23.y * r * g4.w;

    int hd = (tid * 4) & (DH - 1);
    float4 c4 = *(const float4*)(fcp + (long)row * DH + hd);
    float4 s4 = *(const float4*)(fsp + (long)row * DH + hd);
    float o0 = x0 * c4.x - x1 * s4.y;
    float o1 = x0 * s4.y + x1 * c4.x;
    float o2 = x2 * c4.z - x3 * s4.w;
    float o3 = x2 * s4.w + x3 * c4.z;

    __half2 ho01 = __floats2half2_rn(o0, o1);
    __half2 ho23 = __floats2half2_rn(o2, o3);
    *(uint2*)(x + (long)row * DIM + tid * 4) =
        make_uint2(*(unsigned*)&ho01, *(unsigned*)&ho23);
}

// ---------------- block-sparse attention, 4 sub-items per (qb,t,h) (unchanged from R16) ------
#define AQ_OFF   0
#define AK_OFF   34816
#define KV_STAGE 17408
#define AV_OFF   (AK_OFF + 2 * KV_STAGE)
#define ATT_SMEM (AV_OFF + 2 * KV_STAGE)   // 104448

__global__ __launch_bounds__(256, 2) void attention_kernel(
    const __half* __restrict__ q, const __half* __restrict__ k,
    const __half* __restrict__ v, const int* __restrict__ sel,
    float* __restrict__ po, float* __restrict__ pr)
{
    const int qb = blockIdx.x, h = blockIdx.z;
    const int t = blockIdx.y >> 2, sub = blockIdx.y & 3;
    const int kpq = sub & 1, half = sub >> 1;

    int blk = sel[t * 2 + kpq];
    if (blk < 0) return;

    extern __shared__ char asm_[];
    __half* Qh = (__half*)(asm_ + AQ_OFF);

    const int tid = threadIdx.x, warp = tid >> 5, lane = tid & 31;
    const int g = lane >> 2, t4 = lane & 3;

    const int i8 = lane >> 3, r8 = lane & 7;
    const uint32_t smb = smem_u32(asm_);
    const uint32_t qoff = smb + ((warp * 16 + (i8 & 1) * 8 + r8) * 136 + (i8 >> 1) * 8) * 2;
    uint32_t koff_l[4];
    #pragma unroll
    for (int np = 0; np < 4; np++)
        koff_l[np] = ((np * 16 + (i8 >> 1) * 8 + r8) * 136 + (i8 & 1) * 8) * 2;
    const uint32_t voff_l = (((i8 & 1) * 8 + r8) * 136 + (i8 >> 1) * 8) * 2;

    const uint4 z4 = make_uint4(0u, 0u, 0u, 0u);

    const __half* qbase = q + (long)(t * HW) * DIM + (long)h * DH;
    {
        const int c8 = (tid & 15) * 8;
        const int lr0q = tid >> 4;
        #pragma unroll
        for (int i = 0; i < 8; i++) {
            int r = lr0q + i * 16;
            int qr = qb * 128 + r;
            uint4 val = (qr < HW) ? *(const uint4*)(qbase + (long)qr * DIM + c8) : z4;
            *(uint4*)&Qh[r * 136 + c8] = val;
        }
    }

    float oacc[16][4] = {};
    float rp0 = 0.f, rp1 = 0.f;

    const __half* kbp = k + (long)blk * HW * DIM + (long)h * DH;
    const __half* vbp = v + (long)blk * HW * DIM + (long)h * DH;

    const int tstart = half ? 13 : 0;
    const int ntile  = half ? 12 : 13;

    const int lc8 = (tid & 15) * 8;
    const int lr0 = tid >> 4;

    auto issue_tile = [&](int ti) {
        int n0 = (tstart + ti) * 64;
        uint32_t kdst = smb + AK_OFF + (ti & 1) * KV_STAGE;
        uint32_t vdst = smb + AV_OFF + (ti & 1) * KV_STAGE;
        #pragma unroll
        for (int i = 0; i < 4; i++) {
            int r = lr0 + i * 16;
            int kr = n0 + r;
            bool valid = kr < HW;
            long off = valid ? ((long)kr * DIM + lc8) : 0;
            uint32_t d = (r * 136 + lc8) * 2;
            cp_async16(kdst + d, kbp + off, valid);
            cp_async16(vdst + d, vbp + off, valid);
        }
        cp_commit();
    };

    __syncthreads();
    issue_tile(0);

    const float SC   = 0.08838834764831843f * 1.4426950408889634f;
    const float OFFL = 4.0f * 1.4426950408889634f;

    for (int ti = 0; ti < ntile; ti++) {
        if (ti + 1 < ntile) { issue_tile(ti + 1); cp_wait1(); }
        else                { cp_wait0(); }
        __syncthreads();

        const uint32_t Kb = smb + AK_OFF + (ti & 1) * KV_STAGE;
        const uint32_t Vb = smb + AV_OFF + (ti & 1) * KV_STAGE;
        const int n0 = (tstart + ti) * 64;

        float sacc[8][4] = {};
        #pragma unroll
        for (int ks = 0; ks < 8; ks++) {
            const uint32_t kB = ks * 32;
            unsigned a[4], b[4][4];
            ldsm_x4(a, qoff + kB);
            #pragma unroll
            for (int np = 0; np < 4; np++) ldsm_x4(b[np], Kb + koff_l[np] + kB);
            #pragma unroll
            for (int nt = 0; nt < 8; nt++) {
                unsigned b0 = b[nt >> 1][(nt & 1) * 2];
                unsigned b1 = b[nt >> 1][(nt & 1) * 2 + 1];
                mma_f16(sacc[nt], a, b0, b1);
            }
        }

        unsigned ap[4][4];
        #pragma unroll
        for (int nt = 0; nt < 8; nt++) {
            int cn = nt * 8 + 2 * t4;
            bool m0 = (n0 + cn) < HW, m1 = (n0 + cn + 1) < HW;
            float p0 = m0 ? exp2f(fmaf(sacc[nt][0], SC, -OFFL)) : 0.f;
            float p1 = m1 ? exp2f(fmaf(sacc[nt][1], SC, -OFFL)) : 0.f;
            float p2 = m0 ? exp2f(fmaf(sacc[nt][2], SC, -OFFL)) : 0.f;
            float p3 = m1 ? exp2f(fmaf(sacc[nt][3], SC, -OFFL)) : 0.f;
            rp0 += p0 + p1;
            rp1 += p2 + p3;
            __half2 h01 = __floats2half2_rn(p0, p1);
            __half2 h23 = __floats2half2_rn(p2, p3);
            ap[nt >> 1][(nt & 1) * 2 + 0] = *(unsigned*)&h01;
            ap[nt >> 1][(nt & 1) * 2 + 1] = *(unsigned*)&h23;
        }

        #pragma unroll
        for (int kp = 0; kp < 4; kp++) {
            const uint32_t kbase = Vb + voff_l + kp * (16 * 136 * 2);
            #pragma unroll
            for (int nt16 = 0; nt16 < 8; nt16++) {
                unsigned bv[4];
                ldsm_x4_trans(bv, kbase + nt16 * 32);
                mma_f16(oacc[2 * nt16 + 0], ap[kp], bv[0], bv[1]);
                mma_f16(oacc[2 * nt16 + 1], ap[kp], bv[2], bv[3]);
            }
        }
        __syncthreads();
    }

    rp0 += __shfl_xor_sync(0xffffffffu, rp0, 1);
    rp0 += __shfl_xor_sync(0xffffffffu, rp0, 2);
    rp1 += __shfl_xor_sync(0xffffffffu, rp1, 1);
    rp1 += __shfl_xor_sync(0xffffffffu, rp1, 2);

    int qr0 = qb * 128 + warp * 16 + g, qr1 = qr0 + 8;
    long row0 = (long)sub * QTOT + t * HW + qr0;
    long row1 = row0 + 8;
    if (t4 == 0) {
        if (qr0 < HW) pr[row0 * HEADS + h] = rp0;
        if (qr1 < HW) pr[row1 * HEADS + h] = rp1;
    }
    float* pbase = po + (long)h * DH;
    #pragma unroll
    for (int nt = 0; nt < 16; nt++) {
        int d = nt * 8 + 2 * t4;
        if (qr0 < HW)
            *(float2*)(pbase + row0 * DIM + d) = make_float2(oacc[nt][0], oacc[nt][1]);
        if (qr1 < HW)
            *(float2*)(pbase + row1 * DIM + d) = make_float2(oacc[nt][2], oacc[nt][3]);
    }
}

// ---------------- combine partials: out = (sum O) / (sum r) ----------------
__global__ __launch_bounds__(384) void att_combine(
    const float* __restrict__ po, const float* __restrict__ pr,
    const int* __restrict__ sel, __half* __restrict__ out)
{
    const int row = blockIdx.x;
    const int t = row / HW;
    const int c = threadIdx.x * 4;
    const int h = c >> 7;
    const bool v1 = sel[t * 2 + 1] >= 0;

    float4 o = make_float4(0.f, 0.f, 0.f, 0.f);
    float r = 0.f;
    #pragma unroll
    for (int sub = 0; sub < 4; sub++) {
        if ((sub & 1) && !v1) continue;
        long prow = (long)sub * QTOT + row;
        float4 x = *(const float4*)(po + prow * DIM + c);
        o.x += x.x; o.y += x.y; o.z += x.z; o.w += x.w;
        r += pr[prow * HEADS + h];
    }
    float inv = 1.f / r;
    __half2 h01 = __floats2half2_rn(o.x * inv, o.y * inv);
    __half2 h23 = __floats2half2_rn(o.z * inv, o.w * inv);
    *(uint2*)(out + (long)row * DIM + c) =
        make_uint2(*(unsigned*)&h01, *(unsigned*)&h23);
}

// ---------------- launch (6 sequential launches) ----------------
extern "C" void kernel_launch(void* const* d_in, const int* in_sizes, int n_in,
                              void* d_out, int out_size)
{
    const float* hidden  = (const float*)d_in[0];
    const float* history = (const float*)d_in[1];
    const float* fc   = (const float*)d_in[2];
    const float* fs   = (const float*)d_in[3];
    const float* fch  = (const float*)d_in[4];
    const float* fsh  = (const float*)d_in[5];
    const int*   sel  = (const int*)d_in[6];
    const float* Wq = (const float*)d_in[7];
    const float* bq = (const float*)d_in[8];
    const float* Wk = (const float*)d_in[9];
    const float* bk = (const float*)d_in[10];
    const float* Wv = (const float*)d_in[11];
    const float* bv = (const float*)d_in[12];
    const float* Wo = (const float*)d_in[13];
    const float* bo = (const float*)d_in[14];
    const float* gq = (const float*)d_in[15];
    const float* gk = (const float*)d_in[16];
    float* outp = (float*)d_out;

    __half *qp, *kp, *vp, *ap, *hidh, *hish, *wqh, *wkh, *wvh, *woh;
    float *pop, *prp;
    cudaGetSymbolAddress((void**)&qp, g_q);
    cudaGetSymbolAddress((void**)&kp, g_k);
    cudaGetSymbolAddress((void**)&vp, g_v);
    cudaGetSymbolAddress((void**)&ap, g_attn);
    cudaGetSymbolAddress((void**)&hidh, g_hid);
    cudaGetSymbolAddress((void**)&hish, g_his);
    cudaGetSymbolAddress((void**)&wqh, g_wq);
    cudaGetSymbolAddress((void**)&wkh, g_wk);
    cudaGetSymbolAddress((void**)&wvh, g_wv);
    cudaGetSymbolAddress((void**)&woh, g_wo);
    cudaGetSymbolAddress((void**)&pop, g_po);
    cudaGetSymbolAddress((void**)&prp, g_pr);

    cudaFuncSetAttribute(gemm_qkv,
                         cudaFuncAttributeMaxDynamicSharedMemorySize, GEMM_SMEM);
    cudaFuncSetAttribute(gemm_o,
                         cudaFuncAttributeMaxDynamicSharedMemorySize, GEMM_SMEM);
    cudaFuncSetAttribute(attention_kernel,
                         cudaFuncAttributeMaxDynamicSharedMemorySize, ATT_SMEM);

    cvt_all<<<4 * DIM + QTOT + KTOT, 192>>>(
        Wq, Wk, Wv, Wo, hidden, history,
        wqh, wkh, wvh, woh, hidh, hish, sel);

    gemm_qkv<<<dim3(12, 98, 3), 256, GEMM_SMEM>>>(
        hidh, hish, wqh, wkh, wvh, bq, bk, bv, qp, kp, vp, sel);

    rmsnorm_all<<<QTOT + KTOT, 384>>>(qp, kp, gq, gk, fc, fs, fch, fsh, sel);

    attention_kernel<<<dim3(13, TQ * 4, HEADS), 256, ATT_SMEM>>>(qp, kp, vp, sel, pop, prp);

    att_combine<<<QTOT, 384>>>(pop, prp, sel, ap);

    gemm_o<<<dim3(12, 25), 256, GEMM_SMEM>>>(ap, woh, bo, outp);
}